// round 1
// baseline (speedup 1.0000x reference)
#include <cuda_runtime.h>
#include <math.h>

// ---------------- problem constants ----------------
#define BB    2
#define TT    2048
#define HID   4096
#define NH    32
#define NKV   8
#define HD    128
#define MROWS (BB*TT)      // 4096
#define NQ    (NH*HD)      // 4096
#define NKVD  (NKV*HD)     // 1024
#define GROUPS (NH/NKV)    // 4

// ---------------- scratch (device globals, no allocation) ----------------
__device__ float g_q[(size_t)MROWS * NQ];     // 67 MB
__device__ float g_k[(size_t)MROWS * NKVD];   // 17 MB
__device__ float g_v[(size_t)MROWS * NKVD];   // 17 MB
__device__ float g_attn[(size_t)MROWS * NQ];  // 67 MB

// ---------------- fp32 SGEMM: C[M,N] = A[M,K] @ B[K,N] ----------------
// 128x128 block tile, BK=16, 256 threads, 8x8 per-thread microtile.
// All dims must be multiples of 128 (N>=128) and K multiple of 16. True here.
#define GBM 128
#define GBN 128
#define GBK 16
#define GPAD 132   // pad As rows to reduce store bank conflicts

__global__ __launch_bounds__(256) void sgemm_kernel(
    const float* __restrict__ A, const float* __restrict__ B, float* __restrict__ C,
    int M, int N, int K)
{
    __shared__ float As[GBK][GPAD];   // transposed A tile: As[k][m]
    __shared__ float Bs[GBK][GBN];    // Bs[k][n]

    int tid = threadIdx.x;
    int tx = tid & 15;        // 0..15 -> N direction
    int ty = tid >> 4;        // 0..15 -> M direction
    int row0 = blockIdx.y * GBM;
    int col0 = blockIdx.x * GBN;

    float acc[8][8];
#pragma unroll
    for (int i = 0; i < 8; i++)
#pragma unroll
        for (int j = 0; j < 8; j++) acc[i][j] = 0.f;

    for (int kk = 0; kk < K; kk += GBK) {
        // load A tile (128 x 16): 512 float4s, 2 per thread, transpose into As
#pragma unroll
        for (int i = 0; i < 2; i++) {
            int e = tid + i * 256;          // 0..511
            int r = e >> 2;                 // 0..127
            int kc = (e & 3) << 2;          // 0,4,8,12
            float4 a = *(const float4*)&A[(size_t)(row0 + r) * K + kk + kc];
            As[kc + 0][r] = a.x;
            As[kc + 1][r] = a.y;
            As[kc + 2][r] = a.z;
            As[kc + 3][r] = a.w;
        }
        // load B tile (16 x 128): 512 float4s, coalesced
#pragma unroll
        for (int i = 0; i < 2; i++) {
            int e = tid + i * 256;
            int r = e >> 5;                 // 0..15
            int c = (e & 31) << 2;          // 0..124
            *(float4*)&Bs[r][c] = *(const float4*)&B[(size_t)(kk + r) * N + col0 + c];
        }
        __syncthreads();

#pragma unroll
        for (int k = 0; k < GBK; k++) {
            float4 a0 = *(float4*)&As[k][ty * 8];
            float4 a1 = *(float4*)&As[k][ty * 8 + 4];
            float4 b0 = *(float4*)&Bs[k][tx * 8];
            float4 b1 = *(float4*)&Bs[k][tx * 8 + 4];
            float av[8] = {a0.x, a0.y, a0.z, a0.w, a1.x, a1.y, a1.z, a1.w};
            float bv[8] = {b0.x, b0.y, b0.z, b0.w, b1.x, b1.y, b1.z, b1.w};
#pragma unroll
            for (int i = 0; i < 8; i++)
#pragma unroll
                for (int j = 0; j < 8; j++)
                    acc[i][j] += av[i] * bv[j];
        }
        __syncthreads();
    }

#pragma unroll
    for (int i = 0; i < 8; i++) {
        int r = row0 + ty * 8 + i;
#pragma unroll
        for (int j = 0; j < 8; j += 4) {
            float4 v = make_float4(acc[i][j], acc[i][j+1], acc[i][j+2], acc[i][j+3]);
            *(float4*)&C[(size_t)r * N + col0 + tx * 8 + j] = v;
        }
    }
}

// ---------------- fused per-head RMSNorm + RoPE (in place) ----------------
// One block per (b,t,head) row of 128. Row layout: ((b*T + t)*n_heads + h)*128.
__global__ __launch_bounds__(128) void rmsnorm_rope_kernel(
    float* __restrict__ X, const float* __restrict__ w, int n_heads)
{
    int row = blockIdx.x;
    int t = (row / n_heads) % TT;      // position id
    int d = threadIdx.x;
    float* xr = X + (size_t)row * HD;

    float v = xr[d];
    float s = v * v;
#pragma unroll
    for (int off = 16; off; off >>= 1) s += __shfl_xor_sync(0xffffffffu, s, off);

    __shared__ float red[4];
    __shared__ float xs[HD];
    int warp = d >> 5, lane = d & 31;
    if (lane == 0) red[warp] = s;
    __syncthreads();
    float tot = red[0] + red[1] + red[2] + red[3];
    float rinv = rsqrtf(tot * (1.0f / HD) + 1e-6f);
    float xn = w[d] * v * rinv;
    xs[d] = xn;
    __syncthreads();

    if (d < 64) {
        float a = xs[d];
        float b = xs[d + 64];
        // fp64 for pow/sincos: immune to fast-math range reduction at pos<=2047
        double freq = pow(1.0e6, -(double)(2 * d) / 128.0);
        double ang = (double)t * freq;
        double sn, cs;
        sincos(ang, &sn, &cs);
        float fs = (float)sn, fc = (float)cs;
        xr[d]      = a * fc - b * fs;
        xr[d + 64] = b * fc + a * fs;
    }
}

// ---------------- fp32 causal GQA flash attention ----------------
// grid: (T/64, NH, B); 256 threads. BM=BN=64, D=128.
#define FBM 64
#define FBN 64
#define PP  68      // padded pitch for the S/P tile
#define FTHREADS 256

__global__ __launch_bounds__(FTHREADS) void flash_kernel(
    const float* __restrict__ Q, const float* __restrict__ Kb,
    const float* __restrict__ Vb, float* __restrict__ O)
{
    extern __shared__ float smf[];
    float* Qs  = smf;                   // [HD][FBM] transposed
    float* Ks  = Qs + HD * FBM;         // [HD][FBN] transposed
    float* Vs  = Ks + HD * FBN;         // [FBN][HD] row-major
    float* Ps  = Vs + FBN * HD;         // [FBM][PP]
    float* m_s = Ps + FBM * PP;         // [FBM]
    float* l_s = m_s + FBM;             // [FBM]
    float* a_s = l_s + FBM;             // [FBM] per-row alpha

    int tid = threadIdx.x;
    int tx = tid & 15, ty = tid >> 4;
    int lane = tid & 31, warp = tid >> 5;
    int qt0 = blockIdx.x * FBM;
    int h = blockIdx.y;
    int b = blockIdx.z;
    int kvh = h / GROUPS;

    const float* Qp = Q + ((size_t)(b * TT + qt0) * NH + h) * HD;
    // load Q tile transposed: Qs[d][r]
#pragma unroll
    for (int i = 0; i < 8; i++) {
        int e = tid + i * FTHREADS;     // 0..2047
        int r = e >> 5;                 // 0..63
        int c4 = (e & 31) << 2;         // 0..124
        float4 q4 = *(const float4*)&Qp[(size_t)r * NH * HD + c4];
        Qs[(c4 + 0) * FBM + r] = q4.x;
        Qs[(c4 + 1) * FBM + r] = q4.y;
        Qs[(c4 + 2) * FBM + r] = q4.z;
        Qs[(c4 + 3) * FBM + r] = q4.w;
    }
    if (tid < FBM) { m_s[tid] = -1e30f; l_s[tid] = 0.f; }

    float acc[4][8];
#pragma unroll
    for (int i = 0; i < 4; i++)
#pragma unroll
        for (int j = 0; j < 8; j++) acc[i][j] = 0.f;

    int r0 = ty * 4;          // O/S row base
    int cS0 = tx * 4;         // S col base
    int d0 = tx * 8;          // O col base
    const float scale = 0.08838834764831845f;   // 1/sqrt(128)

    int n_kt = qt0 / FBN + 1;  // causal: skip fully-masked tiles
    for (int kt = 0; kt < n_kt; kt++) {
        int kt0 = kt * FBN;
        const float* Kp = Kb + ((size_t)(b * TT + kt0) * NKV + kvh) * HD;
        const float* Vp = Vb + ((size_t)(b * TT + kt0) * NKV + kvh) * HD;

        __syncthreads();   // previous PV done (and Q stores visible on 1st iter)

        // load K transposed + V row-major
#pragma unroll
        for (int i = 0; i < 8; i++) {
            int e = tid + i * FTHREADS;
            int r = e >> 5;
            int c4 = (e & 31) << 2;
            float4 k4 = *(const float4*)&Kp[(size_t)r * NKV * HD + c4];
            Ks[(c4 + 0) * FBN + r] = k4.x;
            Ks[(c4 + 1) * FBN + r] = k4.y;
            Ks[(c4 + 2) * FBN + r] = k4.z;
            Ks[(c4 + 3) * FBN + r] = k4.w;
            float4 v4 = *(const float4*)&Vp[(size_t)r * NKV * HD + c4];
            *(float4*)&Vs[r * HD + c4] = v4;
        }
        __syncthreads();

        // S = scale * Q @ K^T   (4x4 microtile per thread)
        float sacc[4][4];
#pragma unroll
        for (int i = 0; i < 4; i++)
#pragma unroll
            for (int j = 0; j < 4; j++) sacc[i][j] = 0.f;
#pragma unroll 4
        for (int k = 0; k < HD; k++) {
            float4 qa = *(float4*)&Qs[k * FBM + r0];
            float4 ka = *(float4*)&Ks[k * FBN + cS0];
            float qv[4] = {qa.x, qa.y, qa.z, qa.w};
            float kv[4] = {ka.x, ka.y, ka.z, ka.w};
#pragma unroll
            for (int i = 0; i < 4; i++)
#pragma unroll
                for (int j = 0; j < 4; j++)
                    sacc[i][j] += qv[i] * kv[j];
        }
#pragma unroll
        for (int i = 0; i < 4; i++) {
            float4 v = make_float4(sacc[i][0] * scale, sacc[i][1] * scale,
                                   sacc[i][2] * scale, sacc[i][3] * scale);
            *(float4*)&Ps[(r0 + i) * PP + cS0] = v;
        }
        __syncthreads();

        // online softmax: warp w owns rows w*8 .. w*8+7
#pragma unroll
        for (int rr = 0; rr < 8; rr++) {
            int r = warp * 8 + rr;
            int gq = qt0 + r;
            int c0 = lane, c1 = lane + 32;
            bool ok0 = (kt0 + c0) <= gq;
            bool ok1 = (kt0 + c1) <= gq;
            float s0 = ok0 ? Ps[r * PP + c0] : -1e30f;
            float s1 = ok1 ? Ps[r * PP + c1] : -1e30f;
            float mx = fmaxf(s0, s1);
#pragma unroll
            for (int off = 16; off; off >>= 1)
                mx = fmaxf(mx, __shfl_xor_sync(0xffffffffu, mx, off));
            float m_old = m_s[r];
            float m_new = fmaxf(m_old, mx);
            float p0 = ok0 ? expf(s0 - m_new) : 0.f;
            float p1 = ok1 ? expf(s1 - m_new) : 0.f;
            Ps[r * PP + c0] = p0;
            Ps[r * PP + c1] = p1;
            float sum = p0 + p1;
#pragma unroll
            for (int off = 16; off; off >>= 1)
                sum += __shfl_xor_sync(0xffffffffu, sum, off);
            if (lane == 0) {
                float alpha = expf(m_old - m_new);   // 0 on first tile
                l_s[r] = l_s[r] * alpha + sum;
                m_s[r] = m_new;
                a_s[r] = alpha;
            }
        }
        __syncthreads();

        // O = O*alpha + P @ V    (4 rows x 8 cols per thread)
        float al[4];
#pragma unroll
        for (int i = 0; i < 4; i++) {
            al[i] = a_s[r0 + i];
#pragma unroll
            for (int j = 0; j < 8; j++) acc[i][j] *= al[i];
        }
#pragma unroll 2
        for (int c = 0; c < FBN; c++) {
            float4 v0 = *(float4*)&Vs[c * HD + d0];
            float4 v1 = *(float4*)&Vs[c * HD + d0 + 4];
            float vv[8] = {v0.x, v0.y, v0.z, v0.w, v1.x, v1.y, v1.z, v1.w};
#pragma unroll
            for (int i = 0; i < 4; i++) {
                float p = Ps[(r0 + i) * PP + c];
#pragma unroll
                for (int j = 0; j < 8; j++) acc[i][j] += p * vv[j];
            }
        }
    }

    // epilogue: divide by l, write out [b][t][h][d]
#pragma unroll
    for (int i = 0; i < 4; i++) {
        int r = r0 + i;
        float inv = 1.f / l_s[r];
        float* op = O + ((size_t)(b * TT + qt0 + r) * NH + h) * HD + d0;
        float4 o0 = make_float4(acc[i][0] * inv, acc[i][1] * inv, acc[i][2] * inv, acc[i][3] * inv);
        float4 o1 = make_float4(acc[i][4] * inv, acc[i][5] * inv, acc[i][6] * inv, acc[i][7] * inv);
        *(float4*)&op[0] = o0;
        *(float4*)&op[4] = o1;
    }
}

// ---------------- launch ----------------
extern "C" void kernel_launch(void* const* d_in, const int* in_sizes, int n_in,
                              void* d_out, int out_size)
{
    const float* x   = (const float*)d_in[0];
    const float* wq  = (const float*)d_in[1];
    const float* wk  = (const float*)d_in[2];
    const float* wv  = (const float*)d_in[3];
    const float* wo  = (const float*)d_in[4];
    const float* qnw = (const float*)d_in[5];
    const float* knw = (const float*)d_in[6];
    float* out = (float*)d_out;

    float *qb, *kb, *vb, *ab;
    cudaGetSymbolAddress((void**)&qb, g_q);
    cudaGetSymbolAddress((void**)&kb, g_k);
    cudaGetSymbolAddress((void**)&vb, g_v);
    cudaGetSymbolAddress((void**)&ab, g_attn);

    dim3 blk(256);
    // QKV projections
    sgemm_kernel<<<dim3(NQ / GBN, MROWS / GBM), blk>>>(x, wq, qb, MROWS, NQ, HID);
    sgemm_kernel<<<dim3(NKVD / GBN, MROWS / GBM), blk>>>(x, wk, kb, MROWS, NKVD, HID);
    sgemm_kernel<<<dim3(NKVD / GBN, MROWS / GBM), blk>>>(x, wv, vb, MROWS, NKVD, HID);

    // per-head RMSNorm + RoPE (in place)
    rmsnorm_rope_kernel<<<MROWS * NH, 128>>>(qb, qnw, NH);
    rmsnorm_rope_kernel<<<MROWS * NKV, 128>>>(kb, knw, NKV);

    // flash attention
    int smem = (HD * FBM + HD * FBN + FBN * HD + FBM * PP + 3 * FBM) * (int)sizeof(float);
    cudaFuncSetAttribute(flash_kernel, cudaFuncAttributeMaxDynamicSharedMemorySize, smem);
    flash_kernel<<<dim3(TT / FBM, NH, BB), FTHREADS, smem>>>(qb, kb, vb, ab);

    // output projection
    sgemm_kernel<<<dim3(NQ / GBN, MROWS / GBM), blk>>>(ab, wo, out, MROWS, NQ, HID);
}

// round 3
// speedup vs baseline: 1.5022x; 1.5022x over previous
#include <cuda_runtime.h>
#include <cuda_bf16.h>
#include <math.h>
#include <stdint.h>

// ---------------- problem constants ----------------
#define BB    2
#define TT    2048
#define HID   4096
#define NH    32
#define NKV   8
#define HD    128
#define MROWS (BB*TT)      // 4096
#define NQ    (NH*HD)      // 4096
#define NKVD  (NKV*HD)     // 1024
#define GROUPS (NH/NKV)    // 4

// ---------------- scratch (device globals, no allocation) ----------------
__device__ __nv_bfloat16 g_xh[(size_t)MROWS * HID];
__device__ __nv_bfloat16 g_xl[(size_t)MROWS * HID];
__device__ __nv_bfloat16 g_wqt_h[(size_t)NQ * HID],   g_wqt_l[(size_t)NQ * HID];
__device__ __nv_bfloat16 g_wkt_h[(size_t)NKVD * HID], g_wkt_l[(size_t)NKVD * HID];
__device__ __nv_bfloat16 g_wvt_h[(size_t)NKVD * HID], g_wvt_l[(size_t)NKVD * HID];
__device__ __nv_bfloat16 g_wot_h[(size_t)HID * NQ],   g_wot_l[(size_t)HID * NQ];
__device__ __nv_bfloat16 g_ah[(size_t)MROWS * NQ],    g_al[(size_t)MROWS * NQ];
__device__ float g_q[(size_t)MROWS * NQ];
__device__ float g_k[(size_t)MROWS * NKVD];
__device__ float g_v[(size_t)MROWS * NKVD];
__device__ float g_attn[(size_t)MROWS * NQ];

// ---------------- PTX helpers (base ISA only: sm_80-class) ----------------
__device__ __forceinline__ uint32_t smem_u32(const void* p) {
    uint32_t a;
    asm("{ .reg .u64 t; cvta.to.shared.u64 t, %1; cvt.u32.u64 %0, t; }" : "=r"(a) : "l"(p));
    return a;
}

__device__ __forceinline__ void cp16(uint32_t dst, const void* src) {
    asm volatile("cp.async.cg.shared.global [%0], [%1], 16;" :: "r"(dst), "l"(src));
}

__device__ __forceinline__ void ldsm_x4(uint32_t* r, uint32_t addr) {
    asm volatile("ldmatrix.sync.aligned.m8n8.x4.shared.b16 {%0,%1,%2,%3}, [%4];"
                 : "=r"(r[0]), "=r"(r[1]), "=r"(r[2]), "=r"(r[3]) : "r"(addr));
}

__device__ __forceinline__ void mma16816(float* d, const uint32_t* a, const uint32_t* b) {
    asm volatile(
        "mma.sync.aligned.m16n8k16.row.col.f32.bf16.bf16.f32 "
        "{%0,%1,%2,%3}, {%4,%5,%6,%7}, {%8,%9}, {%0,%1,%2,%3};"
        : "+f"(d[0]), "+f"(d[1]), "+f"(d[2]), "+f"(d[3])
        : "r"(a[0]), "r"(a[1]), "r"(a[2]), "r"(a[3]), "r"(b[0]), "r"(b[1]));
}

// ---------------- split/convert kernels ----------------
__global__ __launch_bounds__(256) void convert_split_kernel(
    const float* __restrict__ in, __nv_bfloat16* __restrict__ oh,
    __nv_bfloat16* __restrict__ ol, int n)
{
    int i = blockIdx.x * blockDim.x + threadIdx.x;
    if (i < n) {
        float x = in[i];
        __nv_bfloat16 h = __float2bfloat16(x);
        oh[i] = h;
        ol[i] = __float2bfloat16(x - __bfloat162float(h));
    }
}

// in: fp32 [R, C] row-major -> out hi/lo bf16 [C, R]
__global__ __launch_bounds__(256) void transpose_split_kernel(
    const float* __restrict__ in, __nv_bfloat16* __restrict__ oh,
    __nv_bfloat16* __restrict__ ol, int R, int C)
{
    __shared__ float t[32][33];
    int bx = blockIdx.x * 32;   // C
    int by = blockIdx.y * 32;   // R
    int tx = threadIdx.x, ty = threadIdx.y;   // 32 x 8
#pragma unroll
    for (int j = 0; j < 32; j += 8)
        t[ty + j][tx] = in[(size_t)(by + ty + j) * C + bx + tx];
    __syncthreads();
#pragma unroll
    for (int j = 0; j < 32; j += 8) {
        float x = t[tx][ty + j];
        __nv_bfloat16 h = __float2bfloat16(x);
        size_t o = (size_t)(bx + ty + j) * R + by + tx;
        oh[o] = h;
        ol[o] = __float2bfloat16(x - __bfloat162float(h));
    }
}

// ---------------- mma.sync bf16-split GEMM ----------------
// C[M,N] = Ah@Bh^T + Ah@Bl^T + Al@Bh^T
// A:[M,K] K-major bf16 hi/lo; B:[N,K] K-major bf16 hi/lo (pre-transposed).
// CTA 128x128, BK=64, 8 warps (2x4), warp tile 64x32, 3-stage cp.async.
#define GEMM_BM 128
#define GEMM_BN 128
#define GEMM_BK 64
#define TILE_BYTES (128 * 128)                 // one 128x64 bf16 subtile = 16 KB
#define STAGE_BYTES (4 * TILE_BYTES)           // Ah, Al, Bh, Bl = 64 KB
#define NSTAGE 3
#define GEMM_SMEM (NSTAGE * STAGE_BYTES)       // 192 KB

// swizzled smem addr within a 128x64(bf16) tile: row pitch 128B, 16B chunks xor'd
__device__ __forceinline__ uint32_t sw_addr(uint32_t base, int row, int chunk) {
    return base + row * 128 + ((chunk ^ (row & 7)) << 4);
}

// load 128x64 bf16 subtile via cp.async (4 chunks/thread)
__device__ __forceinline__ void load_tile128(uint32_t sbase, const __nv_bfloat16* g,
                                             int ld, int tid)
{
#pragma unroll
    for (int i = 0; i < 4; i++) {
        int e = tid + i * 256;
        int r = e >> 3;
        int c = e & 7;
        cp16(sw_addr(sbase, r, c), (const void*)(g + (size_t)r * ld + c * 8));
    }
}

__global__ __launch_bounds__(256, 1) void gemm_bf16split_kernel(
    const __nv_bfloat16* __restrict__ Ah, const __nv_bfloat16* __restrict__ Al,
    const __nv_bfloat16* __restrict__ Bh, const __nv_bfloat16* __restrict__ Bl,
    float* __restrict__ C, int M, int N, int K)
{
    extern __shared__ char smem[];
    uint32_t sb = smem_u32(smem);
    int tid = threadIdx.x;
    int warp = tid >> 5, lane = tid & 31;
    int row0 = blockIdx.y * GEMM_BM;
    int col0 = blockIdx.x * GEMM_BN;
    int wm0 = (warp >> 2) * 64;        // warp M offset in tile
    int wn0 = (warp & 3) * 32;         // warp N offset in tile

    const __nv_bfloat16* gAh = Ah + (size_t)row0 * K;
    const __nv_bfloat16* gAl = Al + (size_t)row0 * K;
    const __nv_bfloat16* gBh = Bh + (size_t)col0 * K;
    const __nv_bfloat16* gBl = Bl + (size_t)col0 * K;

    const int T = K / GEMM_BK;

    float acc[4][4][4];   // [m16][n8][frag]
#pragma unroll
    for (int m = 0; m < 4; m++)
#pragma unroll
        for (int n = 0; n < 4; n++)
#pragma unroll
            for (int f = 0; f < 4; f++) acc[m][n][f] = 0.f;

    // prologue: fill stages 0, 1
#pragma unroll
    for (int s = 0; s < 2; s++) {
        uint32_t st = sb + s * STAGE_BYTES;
        int kk = s * GEMM_BK;
        load_tile128(st,                  gAh + kk, K, tid);
        load_tile128(st + TILE_BYTES,     gAl + kk, K, tid);
        load_tile128(st + 2 * TILE_BYTES, gBh + kk, K, tid);
        load_tile128(st + 3 * TILE_BYTES, gBl + kk, K, tid);
        asm volatile("cp.async.commit_group;" ::: "memory");
    }

    // fragment address precompute (per lane)
    int mat = lane >> 3;
    int frow = (lane & 7) + ((mat & 1) << 3);   // row within 16-row group
    int fch  = mat >> 1;                        // chunk within k16 (0 or 1)

    for (int t = 0; t < T; t++) {
        asm volatile("cp.async.wait_group 1;" ::: "memory");
        __syncthreads();

        uint32_t st = sb + (t % NSTAGE) * STAGE_BYTES;
        uint32_t sAh = st, sAl = st + TILE_BYTES;
        uint32_t sBh = st + 2 * TILE_BYTES, sBl = st + 3 * TILE_BYTES;

        // prefetch t+2
        if (t + 2 < T) {
            uint32_t sp = sb + ((t + 2) % NSTAGE) * STAGE_BYTES;
            int kk = (t + 2) * GEMM_BK;
            load_tile128(sp,                  gAh + kk, K, tid);
            load_tile128(sp + TILE_BYTES,     gAl + kk, K, tid);
            load_tile128(sp + 2 * TILE_BYTES, gBh + kk, K, tid);
            load_tile128(sp + 3 * TILE_BYTES, gBl + kk, K, tid);
        }
        asm volatile("cp.async.commit_group;" ::: "memory");

#pragma unroll
        for (int ks = 0; ks < 4; ks++) {
            int kc = ks * 2 + fch;
            // B fragments: two n16 groups cover 32 cols; hi and lo
            uint32_t bh[2][4], bl[2][4];
#pragma unroll
            for (int g = 0; g < 2; g++) {
                int brow = wn0 + g * 16 + frow;
                ldsm_x4(bh[g], sw_addr(sBh, brow, kc));
                ldsm_x4(bl[g], sw_addr(sBl, brow, kc));
            }
#pragma unroll
            for (int m = 0; m < 4; m++) {
                int arow = wm0 + m * 16 + frow;
                uint32_t ah[4], al[4];
                ldsm_x4(ah, sw_addr(sAh, arow, kc));
                ldsm_x4(al, sw_addr(sAl, arow, kc));
#pragma unroll
                for (int n = 0; n < 4; n++) {
                    int g = n >> 1, h = n & 1;
                    uint32_t bhf[2] = {bh[g][h], bh[g][h + 2]};
                    uint32_t blf[2] = {bl[g][h], bl[g][h + 2]};
                    mma16816(acc[m][n], ah, bhf);   // hi*hi
                    mma16816(acc[m][n], ah, blf);   // hi*lo
                    mma16816(acc[m][n], al, bhf);   // lo*hi
                }
            }
        }
        __syncthreads();
    }

    // epilogue: write fp32 C
#pragma unroll
    for (int m = 0; m < 4; m++) {
        int r0 = row0 + wm0 + m * 16 + (lane >> 2);
#pragma unroll
        for (int n = 0; n < 4; n++) {
            int c = col0 + wn0 + n * 8 + (lane & 3) * 2;
            *(float2*)&C[(size_t)r0 * N + c]       = make_float2(acc[m][n][0], acc[m][n][1]);
            *(float2*)&C[(size_t)(r0 + 8) * N + c] = make_float2(acc[m][n][2], acc[m][n][3]);
        }
    }
}

// ---------------- fused per-head RMSNorm + RoPE (in place) ----------------
__global__ __launch_bounds__(128) void rmsnorm_rope_kernel(
    float* __restrict__ X, const float* __restrict__ w, int n_heads)
{
    int row = blockIdx.x;
    int t = (row / n_heads) % TT;
    int d = threadIdx.x;
    float* xr = X + (size_t)row * HD;

    float v = xr[d];
    float s = v * v;
#pragma unroll
    for (int off = 16; off; off >>= 1) s += __shfl_xor_sync(0xffffffffu, s, off);

    __shared__ float red[4];
    __shared__ float xs[HD];
    int warp = d >> 5, lane = d & 31;
    if (lane == 0) red[warp] = s;
    __syncthreads();
    float tot = red[0] + red[1] + red[2] + red[3];
    float rinv = rsqrtf(tot * (1.0f / HD) + 1e-6f);
    float xn = w[d] * v * rinv;
    xs[d] = xn;
    __syncthreads();

    if (d < 64) {
        float a = xs[d];
        float b = xs[d + 64];
        double freq = pow(1.0e6, -(double)(2 * d) / 128.0);
        double ang = (double)t * freq;
        double sn, cs;
        sincos(ang, &sn, &cs);
        float fs = (float)sn, fc = (float)cs;
        xr[d]      = a * fc - b * fs;
        xr[d + 64] = b * fc + a * fs;
    }
}

// ---------------- fp32 causal GQA flash attention ----------------
#define FBM 64
#define FBN 64
#define PP  68
#define FTHREADS 256

__global__ __launch_bounds__(FTHREADS) void flash_kernel(
    const float* __restrict__ Q, const float* __restrict__ Kb,
    const float* __restrict__ Vb, float* __restrict__ O)
{
    extern __shared__ float smf[];
    float* Qs  = smf;
    float* Ks  = Qs + HD * FBM;
    float* Vs  = Ks + HD * FBN;
    float* Ps  = Vs + FBN * HD;
    float* m_s = Ps + FBM * PP;
    float* l_s = m_s + FBM;
    float* a_s = l_s + FBM;

    int tid = threadIdx.x;
    int tx = tid & 15, ty = tid >> 4;
    int lane = tid & 31, warp = tid >> 5;
    int qt0 = blockIdx.x * FBM;
    int h = blockIdx.y;
    int b = blockIdx.z;
    int kvh = h / GROUPS;

    const float* Qp = Q + ((size_t)(b * TT + qt0) * NH + h) * HD;
#pragma unroll
    for (int i = 0; i < 8; i++) {
        int e = tid + i * FTHREADS;
        int r = e >> 5;
        int c4 = (e & 31) << 2;
        float4 q4 = *(const float4*)&Qp[(size_t)r * NH * HD + c4];
        Qs[(c4 + 0) * FBM + r] = q4.x;
        Qs[(c4 + 1) * FBM + r] = q4.y;
        Qs[(c4 + 2) * FBM + r] = q4.z;
        Qs[(c4 + 3) * FBM + r] = q4.w;
    }
    if (tid < FBM) { m_s[tid] = -1e30f; l_s[tid] = 0.f; }

    float acc[4][8];
#pragma unroll
    for (int i = 0; i < 4; i++)
#pragma unroll
        for (int j = 0; j < 8; j++) acc[i][j] = 0.f;

    int r0 = ty * 4;
    int cS0 = tx * 4;
    int d0 = tx * 8;
    const float scale = 0.08838834764831845f;

    int n_kt = qt0 / FBN + 1;
    for (int kt = 0; kt < n_kt; kt++) {
        int kt0 = kt * FBN;
        const float* Kp = Kb + ((size_t)(b * TT + kt0) * NKV + kvh) * HD;
        const float* Vp = Vb + ((size_t)(b * TT + kt0) * NKV + kvh) * HD;

        __syncthreads();

#pragma unroll
        for (int i = 0; i < 8; i++) {
            int e = tid + i * FTHREADS;
            int r = e >> 5;
            int c4 = (e & 31) << 2;
            float4 k4 = *(const float4*)&Kp[(size_t)r * NKV * HD + c4];
            Ks[(c4 + 0) * FBN + r] = k4.x;
            Ks[(c4 + 1) * FBN + r] = k4.y;
            Ks[(c4 + 2) * FBN + r] = k4.z;
            Ks[(c4 + 3) * FBN + r] = k4.w;
            float4 v4 = *(const float4*)&Vp[(size_t)r * NKV * HD + c4];
            *(float4*)&Vs[r * HD + c4] = v4;
        }
        __syncthreads();

        float sacc[4][4];
#pragma unroll
        for (int i = 0; i < 4; i++)
#pragma unroll
            for (int j = 0; j < 4; j++) sacc[i][j] = 0.f;
#pragma unroll 4
        for (int k = 0; k < HD; k++) {
            float4 qa = *(float4*)&Qs[k * FBM + r0];
            float4 ka = *(float4*)&Ks[k * FBN + cS0];
            float qv[4] = {qa.x, qa.y, qa.z, qa.w};
            float kv[4] = {ka.x, ka.y, ka.z, ka.w};
#pragma unroll
            for (int i = 0; i < 4; i++)
#pragma unroll
                for (int j = 0; j < 4; j++)
                    sacc[i][j] += qv[i] * kv[j];
        }
#pragma unroll
        for (int i = 0; i < 4; i++) {
            float4 v = make_float4(sacc[i][0] * scale, sacc[i][1] * scale,
                                   sacc[i][2] * scale, sacc[i][3] * scale);
            *(float4*)&Ps[(r0 + i) * PP + cS0] = v;
        }
        __syncthreads();

#pragma unroll
        for (int rr = 0; rr < 8; rr++) {
            int r = warp * 8 + rr;
            int gq = qt0 + r;
            int c0 = lane, c1 = lane + 32;
            bool ok0 = (kt0 + c0) <= gq;
            bool ok1 = (kt0 + c1) <= gq;
            float s0 = ok0 ? Ps[r * PP + c0] : -1e30f;
            float s1 = ok1 ? Ps[r * PP + c1] : -1e30f;
            float mx = fmaxf(s0, s1);
#pragma unroll
            for (int off = 16; off; off >>= 1)
                mx = fmaxf(mx, __shfl_xor_sync(0xffffffffu, mx, off));
            float m_old = m_s[r];
            float m_new = fmaxf(m_old, mx);
            float p0 = ok0 ? expf(s0 - m_new) : 0.f;
            float p1 = ok1 ? expf(s1 - m_new) : 0.f;
            Ps[r * PP + c0] = p0;
            Ps[r * PP + c1] = p1;
            float sum = p0 + p1;
#pragma unroll
            for (int off = 16; off; off >>= 1)
                sum += __shfl_xor_sync(0xffffffffu, sum, off);
            if (lane == 0) {
                float alpha = expf(m_old - m_new);
                l_s[r] = l_s[r] * alpha + sum;
                m_s[r] = m_new;
                a_s[r] = alpha;
            }
        }
        __syncthreads();

        float al[4];
#pragma unroll
        for (int i = 0; i < 4; i++) {
            al[i] = a_s[r0 + i];
#pragma unroll
            for (int j = 0; j < 8; j++) acc[i][j] *= al[i];
        }
#pragma unroll 2
        for (int c = 0; c < FBN; c++) {
            float4 v0 = *(float4*)&Vs[c * HD + d0];
            float4 v1 = *(float4*)&Vs[c * HD + d0 + 4];
            float vv[8] = {v0.x, v0.y, v0.z, v0.w, v1.x, v1.y, v1.z, v1.w};
#pragma unroll
            for (int i = 0; i < 4; i++) {
                float p = Ps[(r0 + i) * PP + c];
#pragma unroll
                for (int j = 0; j < 8; j++) acc[i][j] += p * vv[j];
            }
        }
    }

#pragma unroll
    for (int i = 0; i < 4; i++) {
        int r = r0 + i;
        float inv = 1.f / l_s[r];
        float* op = O + ((size_t)(b * TT + qt0 + r) * NH + h) * HD + d0;
        float4 o0 = make_float4(acc[i][0] * inv, acc[i][1] * inv, acc[i][2] * inv, acc[i][3] * inv);
        float4 o1 = make_float4(acc[i][4] * inv, acc[i][5] * inv, acc[i][6] * inv, acc[i][7] * inv);
        *(float4*)&op[0] = o0;
        *(float4*)&op[4] = o1;
    }
}

// ---------------- launch ----------------
extern "C" void kernel_launch(void* const* d_in, const int* in_sizes, int n_in,
                              void* d_out, int out_size)
{
    const float* x   = (const float*)d_in[0];
    const float* wq  = (const float*)d_in[1];
    const float* wk  = (const float*)d_in[2];
    const float* wv  = (const float*)d_in[3];
    const float* wo  = (const float*)d_in[4];
    const float* qnw = (const float*)d_in[5];
    const float* knw = (const float*)d_in[6];
    float* out = (float*)d_out;

    __nv_bfloat16 *xh, *xl, *wqth, *wqtl, *wkth, *wktl, *wvth, *wvtl, *woth, *wotl, *ah, *al;
    float *qb, *kb, *vb, *ab;
    cudaGetSymbolAddress((void**)&xh, g_xh);      cudaGetSymbolAddress((void**)&xl, g_xl);
    cudaGetSymbolAddress((void**)&wqth, g_wqt_h); cudaGetSymbolAddress((void**)&wqtl, g_wqt_l);
    cudaGetSymbolAddress((void**)&wkth, g_wkt_h); cudaGetSymbolAddress((void**)&wktl, g_wkt_l);
    cudaGetSymbolAddress((void**)&wvth, g_wvt_h); cudaGetSymbolAddress((void**)&wvtl, g_wvt_l);
    cudaGetSymbolAddress((void**)&woth, g_wot_h); cudaGetSymbolAddress((void**)&wotl, g_wot_l);
    cudaGetSymbolAddress((void**)&ah, g_ah);      cudaGetSymbolAddress((void**)&al, g_al);
    cudaGetSymbolAddress((void**)&qb, g_q);
    cudaGetSymbolAddress((void**)&kb, g_k);
    cudaGetSymbolAddress((void**)&vb, g_v);
    cudaGetSymbolAddress((void**)&ab, g_attn);

    // split x, transpose+split weights
    convert_split_kernel<<<(MROWS * HID + 255) / 256, 256>>>(x, xh, xl, MROWS * HID);
    transpose_split_kernel<<<dim3(NQ / 32, HID / 32), dim3(32, 8)>>>(wq, wqth, wqtl, HID, NQ);
    transpose_split_kernel<<<dim3(NKVD / 32, HID / 32), dim3(32, 8)>>>(wk, wkth, wktl, HID, NKVD);
    transpose_split_kernel<<<dim3(NKVD / 32, HID / 32), dim3(32, 8)>>>(wv, wvth, wvtl, HID, NKVD);
    transpose_split_kernel<<<dim3(HID / 32, NQ / 32), dim3(32, 8)>>>(wo, woth, wotl, NQ, HID);

    cudaFuncSetAttribute(gemm_bf16split_kernel,
                         cudaFuncAttributeMaxDynamicSharedMemorySize, GEMM_SMEM);

    // QKV projections (mma.sync bf16-split)
    gemm_bf16split_kernel<<<dim3(NQ / GEMM_BN, MROWS / GEMM_BM), 256, GEMM_SMEM>>>(
        xh, xl, wqth, wqtl, qb, MROWS, NQ, HID);
    gemm_bf16split_kernel<<<dim3(NKVD / GEMM_BN, MROWS / GEMM_BM), 256, GEMM_SMEM>>>(
        xh, xl, wkth, wktl, kb, MROWS, NKVD, HID);
    gemm_bf16split_kernel<<<dim3(NKVD / GEMM_BN, MROWS / GEMM_BM), 256, GEMM_SMEM>>>(
        xh, xl, wvth, wvtl, vb, MROWS, NKVD, HID);

    // per-head RMSNorm + RoPE (in place)
    rmsnorm_rope_kernel<<<MROWS * NH, 128>>>(qb, qnw, NH);
    rmsnorm_rope_kernel<<<MROWS * NKV, 128>>>(kb, knw, NKV);

    // flash attention (fp32)
    int smem = (HD * FBM + HD * FBN + FBN * HD + FBM * PP + 3 * FBM) * (int)sizeof(float);
    cudaFuncSetAttribute(flash_kernel, cudaFuncAttributeMaxDynamicSharedMemorySize, smem);
    flash_kernel<<<dim3(TT / FBM, NH, BB), FTHREADS, smem>>>(qb, kb, vb, ab);

    // split attn output, then output projection
    convert_split_kernel<<<(MROWS * NQ + 255) / 256, 256>>>(ab, ah, al, MROWS * NQ);
    gemm_bf16split_kernel<<<dim3(HID / GEMM_BN, MROWS / GEMM_BM), 256, GEMM_SMEM>>>(
        ah, al, woth, wotl, out, MROWS, HID, NQ);
}